// round 11
// baseline (speedup 1.0000x reference)
#include <cuda_runtime.h>
#include <cuda_bf16.h>
#include <cstdint>
#include <stdint.h>
#include <math.h>

// ---------------------------------------------------------------------------
// MoE router, single persistent kernel.
// logits = hidden[16384,4096] @ gate_w[8,4096]^T
// softmax -> top2 -> normalized weights; aux loss = 0.01*E*sum(f*P)
// Output (float32, flat): weights[T,2] | experts[T,2] | logits[T,8] | aux
// ---------------------------------------------------------------------------

#define T_TOK     16384
#define HDIM      4096
#define NEXP      8
#define TOK_BLK   16
#define TOK_WARP  4
#define NWARP     4
#define NTHREAD   128
#define CHUNK     256
#define NCHUNK    (HDIM / CHUNK)        /* 16 */
#define NSTAGE    4
#define STAGE_FLOATS (TOK_BLK * CHUNK)  /* 4096 */
#define STAGE_BYTES  (STAGE_FLOATS * 4) /* 16384 */
#define ROW_BYTES    (CHUNK * 4)        /* 1024 */
#define WARP_TX      (TOK_WARP * ROW_BYTES) /* 4096 per-warp tx bytes */
#define SMEM_BYTES   (NSTAGE * STAGE_BYTES) /* 65536 -> 3 CTAs/SM */
#define NBLOCK    (T_TOK / TOK_BLK)     /* 1024 */

#define OUT_W     0
#define OUT_IDX   (T_TOK * 2)
#define OUT_LOG   (T_TOK * 4)
#define OUT_AUX   (T_TOK * 12)

// Tie tolerance + Kahan logits are a proven pair (R5/R7/R9 pass; without
// Kahan one knife-edge token flips). Do not change the arithmetic.
#define TIE_TOL   5e-7f

__device__ float    g_Psum[NEXP];
__device__ unsigned g_Cnt[NEXP];
__device__ unsigned g_done;

__device__ __forceinline__ unsigned su32(const void* p) {
    return (unsigned)__cvta_generic_to_shared(p);
}
__device__ __forceinline__ void mbar_init(unsigned long long* bar, unsigned count) {
    asm volatile("mbarrier.init.shared.b64 [%0], %1;"
                 :: "r"(su32(bar)), "r"(count) : "memory");
}
__device__ __forceinline__ void mbar_expect_tx(unsigned long long* bar, unsigned bytes) {
    asm volatile("mbarrier.arrive.expect_tx.shared.b64 _, [%0], %1;"
                 :: "r"(su32(bar)), "r"(bytes) : "memory");
}
__device__ __forceinline__ void mbar_arrive(unsigned long long* bar) {
    asm volatile("mbarrier.arrive.shared.b64 _, [%0];"
                 :: "r"(su32(bar)) : "memory");
}
__device__ __forceinline__ void mbar_wait(unsigned long long* bar, unsigned parity) {
    const unsigned addr = su32(bar);
    unsigned done = 0;
    while (!done) {
        asm volatile(
            "{\n\t"
            ".reg .pred p;\n\t"
            "mbarrier.try_wait.parity.acquire.cta.shared::cta.b64 p, [%1], %2, 0x989680;\n\t"
            "selp.b32 %0, 1, 0, p;\n\t"
            "}"
            : "=r"(done) : "r"(addr), "r"(parity) : "memory");
    }
}
__device__ __forceinline__ void bulk_cp(void* smem_dst, const void* gmem_src,
                                        unsigned bytes, unsigned long long* bar) {
    asm volatile(
        "cp.async.bulk.shared::cta.global.mbarrier::complete_tx::bytes [%0], [%1], %2, [%3];"
        :: "r"(su32(smem_dst)), "l"(gmem_src), "r"(bytes), "r"(su32(bar)) : "memory");
}

// per-warp producer: warp copies its own 4 token-rows of chunk c
__device__ __forceinline__ void issue_warp(float* buf, unsigned long long* fullB,
                                           const float* gb_base, int c, int row0) {
    const int s = c & (NSTAGE - 1);
    mbar_expect_tx(&fullB[s], WARP_TX);
    float* sb = buf + (size_t)s * STAGE_FLOATS + row0 * CHUNK;
    const float* gb = gb_base + (size_t)row0 * HDIM + c * CHUNK;
    #pragma unroll
    for (int r = 0; r < TOK_WARP; r++)
        bulk_cp(sb + r * CHUNK, gb + (size_t)r * HDIM, ROW_BYTES, &fullB[s]);
}

__global__ void __launch_bounds__(NTHREAD, 3) router_main_kernel(
    const float* __restrict__ hs,    // [T, H]
    const float* __restrict__ gw,    // [E, H]
    float* __restrict__ out)
{
    extern __shared__ float buf[];   // [NSTAGE][TOK_BLK][CHUNK]
    __shared__ unsigned long long fullB[NSTAGE];
    __shared__ unsigned long long emptyB[NSTAGE];
    __shared__ float    sPsum[NEXP];
    __shared__ unsigned sCnt[NEXP];

    const int tid  = threadIdx.x;
    const int warp = tid >> 5;
    const int lane = tid & 31;
    const int row0 = warp * TOK_WARP;
    const size_t tokBase = (size_t)blockIdx.x * TOK_BLK;
    const float* gb_base = hs + tokBase * HDIM;

    if (tid < NEXP) { sPsum[tid] = 0.0f; sCnt[tid] = 0u; }
    if (tid == 0) {
        #pragma unroll
        for (int s = 0; s < NSTAGE; s++) {
            mbar_init(&fullB[s], NWARP);    // 4 warp producers (expect_tx each)
            mbar_init(&emptyB[s], NWARP);   // 4 warp consumers arrive
        }
    }
    __syncthreads();

    if (lane == 0) {
        issue_warp(buf, fullB, gb_base, 0, row0);
        issue_warp(buf, fullB, gb_base, 1, row0);
        issue_warp(buf, fullB, gb_base, 2, row0);
    }

    // Kahan-compensated fp32 accumulators per (expert, token)
    float accS[NEXP][TOK_WARP];
    float accC[NEXP][TOK_WARP];
    #pragma unroll
    for (int e = 0; e < NEXP; e++)
        #pragma unroll
        for (int t = 0; t < TOK_WARP; t++) { accS[e][t] = 0.0f; accC[e][t] = 0.0f; }

    for (int c = 0; c < NCHUNK; c++) {
        const int s = c & (NSTAGE - 1);

        // per-warp refill of slot (c+3)&3 once drained
        if (lane == 0 && c + 3 < NCHUNK) {
            const int cn = c + 3;
            if (cn >= NSTAGE)
                mbar_wait(&emptyB[cn & (NSTAGE - 1)], (unsigned)(((cn >> 2) - 1) & 1));
            issue_warp(buf, fullB, gb_base, cn, row0);
        }

        // wait chunk c's data (completion #(c>>2))
        mbar_wait(&fullB[s], (unsigned)((c >> 2) & 1));

        const float* sb = buf + (size_t)s * STAGE_FLOATS;

        // gate regs: 8 experts x 8 h-values per lane, reused across 4 tokens
        float4 g0[NEXP], g1[NEXP];
        {
            const float* gp = gw + c * CHUNK + lane * 4;
            #pragma unroll
            for (int e = 0; e < NEXP; e++) {
                g0[e] = *(const float4*)(gp + e * HDIM);
                g1[e] = *(const float4*)(gp + e * HDIM + 128);
            }
        }
        #pragma unroll
        for (int t = 0; t < TOK_WARP; t++) {
            const float* bp = sb + (row0 + t) * CHUNK + lane * 4;
            float4 x0 = *(const float4*)bp;
            float4 x1 = *(const float4*)(bp + 128);
            #pragma unroll
            for (int e = 0; e < NEXP; e++) {
                float p = __fmul_rn(x0.x, g0[e].x);
                p = __fmaf_rn(x0.y, g0[e].y, p);
                p = __fmaf_rn(x0.z, g0[e].z, p);
                p = __fmaf_rn(x0.w, g0[e].w, p);
                p = __fmaf_rn(x1.x, g1[e].x, p);
                p = __fmaf_rn(x1.y, g1[e].y, p);
                p = __fmaf_rn(x1.z, g1[e].z, p);
                p = __fmaf_rn(x1.w, g1[e].w, p);
                float y  = __fsub_rn(p, accC[e][t]);
                float t2 = __fadd_rn(accS[e][t], y);
                accC[e][t] = __fsub_rn(__fsub_rn(t2, accS[e][t]), y);
                accS[e][t] = t2;
            }
        }

        if (lane == 0) mbar_arrive(&emptyB[s]);
    }

    // ---- cross-lane reduction in fp64 (exact, same order as before);
    // only the owning lane (lane == t) keeps the result -> no fp64 array.
    float l[NEXP];
    #pragma unroll
    for (int e = 0; e < NEXP; e++) {
        #pragma unroll
        for (int t = 0; t < TOK_WARP; t++) {
            double v = (double)accS[e][t] + (double)accC[e][t];
            v += __shfl_xor_sync(0xFFFFFFFFu, v, 16);
            v += __shfl_xor_sync(0xFFFFFFFFu, v, 8);
            v += __shfl_xor_sync(0xFFFFFFFFu, v, 4);
            v += __shfl_xor_sync(0xFFFFFFFFu, v, 2);
            v += __shfl_xor_sync(0xFFFFFFFFu, v, 1);
            if (lane == t) l[e] = (float)v;
        }
    }

    // ---- epilogue: lanes 0..3 each finish one token
    if (lane < TOK_WARP) {
        const size_t tok = tokBase + row0 + lane;

        float* lg = out + OUT_LOG + tok * NEXP;
        ((float4*)lg)[0] = make_float4(l[0], l[1], l[2], l[3]);
        ((float4*)lg)[1] = make_float4(l[4], l[5], l[6], l[7]);

        float m = l[0];
        #pragma unroll
        for (int e = 1; e < NEXP; e++) m = fmaxf(m, l[e]);
        float p[NEXP], sum = 0.0f;
        #pragma unroll
        for (int e = 0; e < NEXP; e++) { p[e] = expf(l[e] - m); sum += p[e]; }
        const float inv = 1.0f / sum;

        int i1 = 0;
        #pragma unroll
        for (int e = 1; e < NEXP; e++) if (p[e] > p[i1] + TIE_TOL) i1 = e;
        int i2 = (i1 == 0) ? 1 : 0;
        #pragma unroll
        for (int e = 0; e < NEXP; e++)
            if (e != i1 && e != i2 && p[e] > p[i2] + TIE_TOL) i2 = e;
        const float v1 = p[i1];
        const float v2 = p[i2];

        const float winv = 1.0f / (v1 + v2);
        out[OUT_W   + tok * 2 + 0] = v1 * winv;
        out[OUT_W   + tok * 2 + 1] = v2 * winv;
        out[OUT_IDX + tok * 2 + 0] = (float)i1;
        out[OUT_IDX + tok * 2 + 1] = (float)i2;

        #pragma unroll
        for (int e = 0; e < NEXP; e++) atomicAdd(&sPsum[e], p[e] * inv);
        atomicAdd(&sCnt[i1], 1u);
    }
    __syncthreads();

    // ---- aux-loss: tid 0 pushes this block's partials, then last block
    //      finalizes and resets scratch (canonical fence+counter pattern).
    if (tid == 0) {
        #pragma unroll
        for (int e = 0; e < NEXP; e++) {
            atomicAdd(&g_Psum[e], sPsum[e]);
            atomicAdd(&g_Cnt[e],  sCnt[e]);
        }
        __threadfence();
        const unsigned prev = atomicAdd(&g_done, 1u);
        if (prev == NBLOCK - 1) {
            float s = 0.0f;
            const float invT = 1.0f / (float)T_TOK;
            #pragma unroll
            for (int e = 0; e < NEXP; e++) {
                const float P = atomicAdd(&g_Psum[e], 0.0f) * invT;
                const float f = (float)atomicAdd(&g_Cnt[e], 0u) * invT;
                s += f * P;
            }
            out[OUT_AUX] = 0.01f * (float)NEXP * s;
            // reset scratch for next (graph-replayed) launch
            #pragma unroll
            for (int e = 0; e < NEXP; e++) { g_Psum[e] = 0.0f; g_Cnt[e] = 0u; }
            __threadfence();
            g_done = 0u;
        }
    }
}

extern "C" void kernel_launch(void* const* d_in, const int* in_sizes, int n_in,
                              void* d_out, int out_size) {
    const float* hs = (const float*)d_in[0];
    const float* gw = (const float*)d_in[1];
    if (n_in >= 2 && in_sizes[0] < in_sizes[1]) {
        const float* tmp = hs; hs = gw; gw = tmp;
    }
    float* out = (float*)d_out;

    cudaFuncSetAttribute(router_main_kernel,
                         cudaFuncAttributeMaxDynamicSharedMemorySize, SMEM_BYTES);

    router_main_kernel<<<NBLOCK, NTHREAD, SMEM_BYTES>>>(hs, gw, out);
}

// round 12
// speedup vs baseline: 1.1267x; 1.1267x over previous
#include <cuda_runtime.h>
#include <cuda_bf16.h>
#include <cstdint>
#include <stdint.h>
#include <math.h>

// ---------------------------------------------------------------------------
// MoE router, single kernel.
// logits = hidden[16384,4096] @ gate_w[8,4096]^T
// softmax -> top2 -> normalized weights; aux loss = 0.01*E*sum(f*P)
// Output (float32, flat): weights[T,2] | experts[T,2] | logits[T,8] | aux
//
// Memory path: 4KB cp.async.bulk requests (quarter token-row) -> 4x the
// request-rate-limited bandwidth of the previous 1KB-request design.
// ---------------------------------------------------------------------------

#define T_TOK     16384
#define HDIM      4096
#define NEXP      8
#define TOK_BLK   8
#define TOK_WARP  2
#define NWARP     4
#define NTHREAD   128
#define NBLOCK    (T_TOK / TOK_BLK)      /* 2048 */

#define OUTER     4                      /* h super-chunks of 1024 floats */
#define SUBC      4                      /* 256-float subchunks per super  */
#define CHUNK     256
#define ROW_FLOATS   1024                /* per-stage floats per token row */
#define ROW_BYTES    (ROW_FLOATS * 4)    /* 4096 = one bulk request        */
#define STAGE_FLOATS (TOK_BLK * ROW_FLOATS)   /* 8192  */
#define STAGE_BYTES  (STAGE_FLOATS * 4)       /* 32768 */
#define NSTAGE    3
#define SMEM_BYTES   (NSTAGE * STAGE_BYTES)   /* 98304 -> 2 CTAs/SM */
#define WARP_TX      (TOK_WARP * ROW_BYTES)   /* 8192 per-warp tx   */

#define OUT_W     0
#define OUT_IDX   (T_TOK * 2)
#define OUT_LOG   (T_TOK * 4)
#define OUT_AUX   (T_TOK * 12)

// Tie tolerance + Kahan logits are a proven pair (R5/R7/R9/R10 pass; without
// Kahan one knife-edge token flips). Arithmetic below is bit-identical to
// those passing kernels (same subchunk order, same lane mapping).
#define TIE_TOL   5e-7f

__device__ float    g_Psum[NEXP];
__device__ unsigned g_Cnt[NEXP];
__device__ unsigned g_done;

__device__ __forceinline__ unsigned su32(const void* p) {
    return (unsigned)__cvta_generic_to_shared(p);
}
__device__ __forceinline__ void mbar_init(unsigned long long* bar, unsigned count) {
    asm volatile("mbarrier.init.shared.b64 [%0], %1;"
                 :: "r"(su32(bar)), "r"(count) : "memory");
}
__device__ __forceinline__ void mbar_expect_tx(unsigned long long* bar, unsigned bytes) {
    asm volatile("mbarrier.arrive.expect_tx.shared.b64 _, [%0], %1;"
                 :: "r"(su32(bar)), "r"(bytes) : "memory");
}
__device__ __forceinline__ void mbar_arrive(unsigned long long* bar) {
    asm volatile("mbarrier.arrive.shared.b64 _, [%0];"
                 :: "r"(su32(bar)) : "memory");
}
__device__ __forceinline__ void mbar_wait(unsigned long long* bar, unsigned parity) {
    const unsigned addr = su32(bar);
    unsigned done = 0;
    while (!done) {
        asm volatile(
            "{\n\t"
            ".reg .pred p;\n\t"
            "mbarrier.try_wait.parity.acquire.cta.shared::cta.b64 p, [%1], %2, 0x989680;\n\t"
            "selp.b32 %0, 1, 0, p;\n\t"
            "}"
            : "=r"(done) : "r"(addr), "r"(parity) : "memory");
    }
}
__device__ __forceinline__ void bulk_cp(void* smem_dst, const void* gmem_src,
                                        unsigned bytes, unsigned long long* bar) {
    asm volatile(
        "cp.async.bulk.shared::cta.global.mbarrier::complete_tx::bytes [%0], [%1], %2, [%3];"
        :: "r"(su32(smem_dst)), "l"(gmem_src), "r"(bytes), "r"(su32(bar)) : "memory");
}

// per-warp producer: copies this warp's 2 token-rows (4KB each) of outer o
__device__ __forceinline__ void issue_warp(float* buf, unsigned long long* fullB,
                                           const float* gb_base, int o, int row0) {
    const int s = o % NSTAGE;
    mbar_expect_tx(&fullB[s], WARP_TX);
    float* sb = buf + (size_t)s * STAGE_FLOATS;
    #pragma unroll
    for (int r = 0; r < TOK_WARP; r++)
        bulk_cp(sb + (row0 + r) * ROW_FLOATS,
                gb_base + (size_t)(row0 + r) * HDIM + o * ROW_FLOATS,
                ROW_BYTES, &fullB[s]);
}

__global__ void __launch_bounds__(NTHREAD, 2) router_main_kernel(
    const float* __restrict__ hs,    // [T, H]
    const float* __restrict__ gw,    // [E, H]
    float* __restrict__ out)
{
    extern __shared__ float buf[];   // [NSTAGE][TOK_BLK][ROW_FLOATS]
    __shared__ unsigned long long fullB[NSTAGE];
    __shared__ unsigned long long emptyB[NSTAGE];
    __shared__ float    sPsum[NEXP];
    __shared__ unsigned sCnt[NEXP];

    const int tid  = threadIdx.x;
    const int warp = tid >> 5;
    const int lane = tid & 31;
    const int row0 = warp * TOK_WARP;
    const size_t tokBase = (size_t)blockIdx.x * TOK_BLK;
    const float* gb_base = hs + tokBase * HDIM;

    if (tid < NEXP) { sPsum[tid] = 0.0f; sCnt[tid] = 0u; }
    if (tid == 0) {
        #pragma unroll
        for (int s = 0; s < NSTAGE; s++) {
            mbar_init(&fullB[s], NWARP);    // 4 warp producers (expect_tx each)
            mbar_init(&emptyB[s], NWARP);   // 4 warp consumers arrive
        }
    }
    __syncthreads();

    // prefetch all 3 ring slots (48KB in flight per CTA)
    if (lane == 0) {
        issue_warp(buf, fullB, gb_base, 0, row0);
        issue_warp(buf, fullB, gb_base, 1, row0);
        issue_warp(buf, fullB, gb_base, 2, row0);
    }

    // Kahan-compensated fp32 accumulators per (expert, token)
    float accS[NEXP][TOK_WARP];
    float accC[NEXP][TOK_WARP];
    #pragma unroll
    for (int e = 0; e < NEXP; e++)
        #pragma unroll
        for (int t = 0; t < TOK_WARP; t++) { accS[e][t] = 0.0f; accC[e][t] = 0.0f; }

    for (int o = 0; o < OUTER; o++) {
        const int s = o % NSTAGE;

        // wait for super-chunk o's 32KB (completion #(o/NSTAGE))
        mbar_wait(&fullB[s], (unsigned)((o / NSTAGE) & 1));

        const float* sb = buf + (size_t)s * STAGE_FLOATS;

        #pragma unroll
        for (int k = 0; k < SUBC; k++) {
            const int c = o * SUBC + k;   // global 256-float subchunk index

            // gate regs: 8 experts x 8 h-values per lane, reused across tokens
            float4 g0[NEXP], g1[NEXP];
            {
                const float* gp = gw + c * CHUNK + lane * 4;
                #pragma unroll
                for (int e = 0; e < NEXP; e++) {
                    g0[e] = *(const float4*)(gp + e * HDIM);
                    g1[e] = *(const float4*)(gp + e * HDIM + 128);
                }
            }
            #pragma unroll
            for (int t = 0; t < TOK_WARP; t++) {
                const float* bp = sb + (row0 + t) * ROW_FLOATS + k * CHUNK + lane * 4;
                float4 x0 = *(const float4*)bp;
                float4 x1 = *(const float4*)(bp + 128);
                #pragma unroll
                for (int e = 0; e < NEXP; e++) {
                    float p = __fmul_rn(x0.x, g0[e].x);
                    p = __fmaf_rn(x0.y, g0[e].y, p);
                    p = __fmaf_rn(x0.z, g0[e].z, p);
                    p = __fmaf_rn(x0.w, g0[e].w, p);
                    p = __fmaf_rn(x1.x, g1[e].x, p);
                    p = __fmaf_rn(x1.y, g1[e].y, p);
                    p = __fmaf_rn(x1.z, g1[e].z, p);
                    p = __fmaf_rn(x1.w, g1[e].w, p);
                    float y  = __fsub_rn(p, accC[e][t]);
                    float t2 = __fadd_rn(accS[e][t], y);
                    accC[e][t] = __fsub_rn(__fsub_rn(t2, accS[e][t]), y);
                    accS[e][t] = t2;
                }
            }
        }

        if (lane == 0) {
            mbar_arrive(&emptyB[s]);
            if (o + NSTAGE < OUTER) {   // only o==0 -> refill slot 0 with o=3
                mbar_wait(&emptyB[s], (unsigned)((o / NSTAGE) & 1));
                issue_warp(buf, fullB, gb_base, o + NSTAGE, row0);
            }
        }
    }

    // ---- cross-lane reduction in fp64 (exact); owning lane keeps result
    float l[NEXP];
    #pragma unroll
    for (int e = 0; e < NEXP; e++) {
        #pragma unroll
        for (int t = 0; t < TOK_WARP; t++) {
            double v = (double)accS[e][t] + (double)accC[e][t];
            v += __shfl_xor_sync(0xFFFFFFFFu, v, 16);
            v += __shfl_xor_sync(0xFFFFFFFFu, v, 8);
            v += __shfl_xor_sync(0xFFFFFFFFu, v, 4);
            v += __shfl_xor_sync(0xFFFFFFFFu, v, 2);
            v += __shfl_xor_sync(0xFFFFFFFFu, v, 1);
            if (lane == t) l[e] = (float)v;
        }
    }

    // ---- epilogue: lanes 0..1 each finish one token
    if (lane < TOK_WARP) {
        const size_t tok = tokBase + row0 + lane;

        float* lg = out + OUT_LOG + tok * NEXP;
        ((float4*)lg)[0] = make_float4(l[0], l[1], l[2], l[3]);
        ((float4*)lg)[1] = make_float4(l[4], l[5], l[6], l[7]);

        float m = l[0];
        #pragma unroll
        for (int e = 1; e < NEXP; e++) m = fmaxf(m, l[e]);
        float p[NEXP], sum = 0.0f;
        #pragma unroll
        for (int e = 0; e < NEXP; e++) { p[e] = expf(l[e] - m); sum += p[e]; }
        const float inv = 1.0f / sum;

        int i1 = 0;
        #pragma unroll
        for (int e = 1; e < NEXP; e++) if (p[e] > p[i1] + TIE_TOL) i1 = e;
        int i2 = (i1 == 0) ? 1 : 0;
        #pragma unroll
        for (int e = 0; e < NEXP; e++)
            if (e != i1 && e != i2 && p[e] > p[i2] + TIE_TOL) i2 = e;
        const float v1 = p[i1];
        const float v2 = p[i2];

        const float winv = 1.0f / (v1 + v2);
        out[OUT_W   + tok * 2 + 0] = v1 * winv;
        out[OUT_W   + tok * 2 + 1] = v2 * winv;
        out[OUT_IDX + tok * 2 + 0] = (float)i1;
        out[OUT_IDX + tok * 2 + 1] = (float)i2;

        #pragma unroll
        for (int e = 0; e < NEXP; e++) atomicAdd(&sPsum[e], p[e] * inv);
        atomicAdd(&sCnt[i1], 1u);
    }
    __syncthreads();

    // ---- aux-loss: push partials; last block finalizes + resets scratch
    if (tid == 0) {
        #pragma unroll
        for (int e = 0; e < NEXP; e++) {
            atomicAdd(&g_Psum[e], sPsum[e]);
            atomicAdd(&g_Cnt[e],  sCnt[e]);
        }
        __threadfence();
        const unsigned prev = atomicAdd(&g_done, 1u);
        if (prev == NBLOCK - 1) {
            float s = 0.0f;
            const float invT = 1.0f / (float)T_TOK;
            #pragma unroll
            for (int e = 0; e < NEXP; e++) {
                const float P = atomicAdd(&g_Psum[e], 0.0f) * invT;
                const float f = (float)atomicAdd(&g_Cnt[e], 0u) * invT;
                s += f * P;
            }
            out[OUT_AUX] = 0.01f * (float)NEXP * s;
            #pragma unroll
            for (int e = 0; e < NEXP; e++) { g_Psum[e] = 0.0f; g_Cnt[e] = 0u; }
            __threadfence();
            g_done = 0u;
        }
    }
}

extern "C" void kernel_launch(void* const* d_in, const int* in_sizes, int n_in,
                              void* d_out, int out_size) {
    const float* hs = (const float*)d_in[0];
    const float* gw = (const float*)d_in[1];
    if (n_in >= 2 && in_sizes[0] < in_sizes[1]) {
        const float* tmp = hs; hs = gw; gw = tmp;
    }
    float* out = (float*)d_out;

    cudaFuncSetAttribute(router_main_kernel,
                         cudaFuncAttributeMaxDynamicSharedMemorySize, SMEM_BYTES);

    router_main_kernel<<<NBLOCK, NTHREAD, SMEM_BYTES>>>(hs, gw, out);
}